// round 10
// baseline (speedup 1.0000x reference)
#include <cuda_runtime.h>
#include <math.h>

#define BB 512
#define TT 128
#define FF 128
#define HH 256
#define NS 127   // T-1 scan steps

// ---------------- scratch (static device memory; no allocations) ----------------
__device__ float g_vhat[BB*TT*FF];            // values_hat           [b][t][f]  (32MB)
__device__ float g_gamma[BB*TT*HH];           // gamma                [b][t][h]  (64MB)
__device__ float g_zx[NS*BB*4*HH];            // input-gate preact    [t][b][n]  (254MB)
__device__ float g_H[(NS+1)*BB*HH];           // h history, slot0=h0  [t][b][h]  (64MB)
__device__ float g_c[BB*HH];                  // cell state
__device__ float g_invden[NS];
__device__ double g_loss;

__device__ __forceinline__ float sigf(float x){ return 1.f/(1.f+expf(-x)); }

// ---------------- init: h0 = c0 = 0, loss = 0 ----------------
__global__ void k_init()
{
    int i = blockIdx.x*256 + threadIdx.x;
    if (i < BB*HH){ g_c[i] = 0.f; g_H[i] = 0.f; }
    if (i == 0) g_loss = 0.0;
}

// ---------------- per-step loss denominators: 1/(sum(masks[:,t+1])+1e-5) ----------------
__global__ void k_invden(const float* __restrict__ masks)
{
    int t = blockIdx.x;              // 0..126, uses masks at time t+1
    float s = 0.f;
    for (int i = threadIdx.x; i < BB*FF; i += 256){
        int b = i >> 7, f = i & 127;
        s += masks[(b*TT + (t+1))*FF + f];
    }
    __shared__ float red[256];
    red[threadIdx.x] = s; __syncthreads();
    for (int off = 128; off > 0; off >>= 1){
        if (threadIdx.x < off) red[threadIdx.x] += red[threadIdx.x+off];
        __syncthreads();
    }
    if (threadIdx.x == 0) g_invden[t] = 1.f/(red[0] + 1e-5f);
}

// ---------------- values_hat: feature + temporal regression fused ----------------
// one block per batch b; V, feat_W, temp_W all resident in smem (203KB)
__global__ __launch_bounds__(256) void k_vhat(
    const float* __restrict__ values, const float* __restrict__ masks,
    const float* __restrict__ featW,  const float* __restrict__ featb,
    const float* __restrict__ tempW,  const float* __restrict__ tempb)
{
    extern __shared__ float sm[];
    float* Vs = sm;                // [128][132]
    float* Wf = sm + 128*132;      // [128][132]
    float* Wt = sm + 2*128*132;    // [128][132]
    const int b = blockIdx.x, tid = threadIdx.x;
    const float4* v4 = (const float4*)(values + b*TT*FF);
    const float4* f4 = (const float4*)featW;
    const float4* t4 = (const float4*)tempW;
#pragma unroll
    for (int q = 0; q < 16; q++){
        int i4 = tid + q*256;
        int row = i4 >> 5, c4 = i4 & 31;
        *(float4*)&Vs[row*132 + c4*4] = v4[i4];
        *(float4*)&Wf[row*132 + c4*4] = f4[i4];
        *(float4*)&Wt[row*132 + c4*4] = t4[i4];
    }
    __syncthreads();
    const int tx = tid & 15, ty = tid >> 4;
    float acc[8][8];
#pragma unroll
    for (int i=0;i<8;i++)
#pragma unroll
        for (int j=0;j<8;j++) acc[i][j] = 0.f;

    // pass 1: acc[t][g] += V[t][k] * featW[g][k]
    for (int k0 = 0; k0 < 128; k0 += 4){
        float4 a[8], w[8];
#pragma unroll
        for (int i=0;i<8;i++) a[i] = *(const float4*)&Vs[(ty+16*i)*132 + k0];
#pragma unroll
        for (int j=0;j<8;j++) w[j] = *(const float4*)&Wf[(tx+16*j)*132 + k0];
#pragma unroll
        for (int i=0;i<8;i++)
#pragma unroll
            for (int j=0;j<8;j++)
                acc[i][j] += a[i].x*w[j].x + a[i].y*w[j].y + a[i].z*w[j].z + a[i].w*w[j].w;
    }
    // pass 2: acc[t][g] += tempW[t][s] * V[s][g]
    for (int k0 = 0; k0 < 128; k0 += 4){
        float4 a[8];
#pragma unroll
        for (int i=0;i<8;i++) a[i] = *(const float4*)&Wt[(ty+16*i)*132 + k0];
#pragma unroll
        for (int kk=0;kk<4;kk++){
            float vg[8];
#pragma unroll
            for (int j=0;j<8;j++) vg[j] = Vs[(k0+kk)*132 + tx + 16*j];
#pragma unroll
            for (int i=0;i<8;i++){
                float av = (kk==0)?a[i].x:(kk==1)?a[i].y:(kk==2)?a[i].z:a[i].w;
#pragma unroll
                for (int j=0;j<8;j++) acc[i][j] += av * vg[j];
            }
        }
    }
    const float* mrow = masks + b*TT*FF;
#pragma unroll
    for (int i=0;i<8;i++){
        int t = ty + 16*i;
        float tb  = tempb[t];
        float wtd = Wt[t*132 + t];
#pragma unroll
        for (int j=0;j<8;j++){
            int g = tx + 16*j;
            float v  = Vs[t*132 + g];
            float vh = acc[i][j] - v*(Wf[g*132 + g] + wtd) + featb[g] + tb;
            float m  = mrow[t*FF + g];
            g_vhat[(b*TT + t)*FF + g] = v*m + vh*(1.f - m);
        }
    }
}

// ---------------- gamma = exp(-|deltas @ decay_W^T + b|) ----------------
// tile: 128 rows x 64 h, K=128 resident
__global__ __launch_bounds__(256) void k_gamma(
    const float* __restrict__ deltas, const float* __restrict__ decayW,
    const float* __restrict__ decayb)
{
    extern __shared__ float sm[];
    float* As = sm;               // [128][132]
    float* Bs = sm + 128*132;     // [64][132]
    const int r0 = blockIdx.x*128, h0 = blockIdx.y*64, tid = threadIdx.x;
    const float4* a4 = (const float4*)(deltas + r0*FF);
#pragma unroll
    for (int q=0;q<16;q++){
        int i4 = tid + q*256;
        int row = i4 >> 5, c4 = i4 & 31;
        *(float4*)&As[row*132 + c4*4] = a4[i4];
    }
    const float4* b4 = (const float4*)(decayW + h0*FF);
#pragma unroll
    for (int q=0;q<8;q++){
        int i4 = tid + q*256;
        int row = i4 >> 5, c4 = i4 & 31;
        *(float4*)&Bs[row*132 + c4*4] = b4[i4];
    }
    __syncthreads();
    const int tx = tid & 15, ty = tid >> 4;
    float acc[8][4];
#pragma unroll
    for (int i=0;i<8;i++)
#pragma unroll
        for (int q=0;q<4;q++) acc[i][q]=0.f;
    for (int k0=0;k0<128;k0+=4){
        float4 a[8], w[4];
#pragma unroll
        for (int i=0;i<8;i++) a[i] = *(const float4*)&As[(ty+16*i)*132 + k0];
#pragma unroll
        for (int q=0;q<4;q++) w[q] = *(const float4*)&Bs[(tx+16*q)*132 + k0];
#pragma unroll
        for (int i=0;i<8;i++)
#pragma unroll
            for (int q=0;q<4;q++)
                acc[i][q] += a[i].x*w[q].x + a[i].y*w[q].y + a[i].z*w[q].z + a[i].w*w[q].w;
    }
#pragma unroll
    for (int i=0;i<8;i++){
        int r = r0 + ty + 16*i;
#pragma unroll
        for (int q=0;q<4;q++){
            int h = h0 + tx + 16*q;
            g_gamma[r*HH + h] = expf(-fabsf(acc[i][q] + decayb[h]));
        }
    }
}

// ---------------- zx = [values_hat, masks] @ W_ih^T + b_ih + b_hh (all steps at once) ----------------
// M=65024 (r=t*512+b), N=1024, K=256 (2 chunks of 128)
__global__ __launch_bounds__(256) void k_zx(
    const float* __restrict__ masks, const float* __restrict__ Wih,
    const float* __restrict__ bih,   const float* __restrict__ bhh)
{
    extern __shared__ float sm[];
    float* As = sm;               // [128][132]
    float* Bs = sm + 128*132;     // [128][132]
    const int r0 = blockIdx.x*128, n0 = blockIdx.y*128, tid = threadIdx.x;
    const int tx = tid & 15, ty = tid >> 4;
    float acc[8][8];
#pragma unroll
    for (int i=0;i<8;i++)
#pragma unroll
        for (int j=0;j<8;j++) acc[i][j]=0.f;

    for (int kc = 0; kc < 2; kc++){
#pragma unroll
        for (int q=0;q<16;q++){
            int i4 = tid + q*256;
            int row = i4 >> 5, c4 = i4 & 31;
            int r = r0 + row;
            int t = r >> 9, b = r & 511;
            const float* src = (kc==0) ? g_vhat : masks;
            *(float4*)&As[row*132 + c4*4] = *(const float4*)&src[(b*TT + t)*FF + c4*4];
            *(float4*)&Bs[row*132 + c4*4] = *(const float4*)&Wih[(n0+row)*256 + kc*128 + c4*4];
        }
        __syncthreads();
        for (int k0=0;k0<128;k0+=4){
            float4 a[8], w[8];
#pragma unroll
            for (int i=0;i<8;i++) a[i] = *(const float4*)&As[(ty+16*i)*132 + k0];
#pragma unroll
            for (int j=0;j<8;j++) w[j] = *(const float4*)&Bs[(tx+16*j)*132 + k0];
#pragma unroll
            for (int i=0;i<8;i++)
#pragma unroll
                for (int j=0;j<8;j++)
                    acc[i][j] += a[i].x*w[j].x + a[i].y*w[j].y + a[i].z*w[j].z + a[i].w*w[j].w;
        }
        __syncthreads();
    }
#pragma unroll
    for (int i=0;i<8;i++){
        int r = r0 + ty + 16*i;
#pragma unroll
        for (int j=0;j<8;j++){
            int n = n0 + tx + 16*j;
            g_zx[r*1024 + n] = acc[i][j] + bih[n] + bhh[n];
        }
    }
}

// ---------------- one LSTM scan step: h' , c' from h*gamma, zx[t], W_hh ----------------
// grid (16,8): b-tile 32, j-tile 32 (x4 gates). 128 threads, 166KB smem.
__global__ __launch_bounds__(128) void k_step(const float* __restrict__ Whh, int t)
{
    extern __shared__ float sm[];
    float* hs = sm;              // [32][260]  decayed h
    float* ws = sm + 32*260;     // [128][260] 4 gates x 32 j rows of W_hh
    const int b0 = blockIdx.x*32, j0 = blockIdx.y*32, tid = threadIdx.x;
#pragma unroll
    for (int q=0;q<16;q++){
        int i4 = tid + q*128;
        int row = i4 >> 6, c4 = i4 & 63;
        int b = b0 + row;
        float4 hv = *(const float4*)&g_H[(t*512 + b)*256 + c4*4];
        float4 gv = *(const float4*)&g_gamma[(b*TT + t)*HH + c4*4];
        float4 o; o.x=hv.x*gv.x; o.y=hv.y*gv.y; o.z=hv.z*gv.z; o.w=hv.w*gv.w;
        *(float4*)&hs[row*260 + c4*4] = o;
    }
#pragma unroll
    for (int q=0;q<64;q++){
        int i4 = tid + q*128;
        int row = i4 >> 6, c4 = i4 & 63;
        int gate = row >> 5, jj = row & 31;
        *(float4*)&ws[row*260 + c4*4] = *(const float4*)&Whh[(gate*256 + j0 + jj)*256 + c4*4];
    }
    __syncthreads();
    const int tx = tid & 15, ty = tid >> 4;   // ty 0..7
    float acc[4][2][4];
#pragma unroll
    for (int i=0;i<4;i++)
#pragma unroll
        for (int q=0;q<2;q++)
#pragma unroll
            for (int g=0;g<4;g++) acc[i][q][g]=0.f;

    for (int k0=0;k0<256;k0+=4){
        float4 a[4];
#pragma unroll
        for (int i=0;i<4;i++) a[i] = *(const float4*)&hs[(ty*4+i)*260 + k0];
#pragma unroll
        for (int q=0;q<2;q++)
#pragma unroll
            for (int g=0;g<4;g++){
                float4 w = *(const float4*)&ws[(g*32 + tx + 16*q)*260 + k0];
#pragma unroll
                for (int i=0;i<4;i++)
                    acc[i][q][g] += a[i].x*w.x + a[i].y*w.y + a[i].z*w.z + a[i].w*w.w;
            }
    }
#pragma unroll
    for (int i=0;i<4;i++){
        int b = b0 + ty*4 + i;
        const float* zr = g_zx + (t*512 + b)*1024;
#pragma unroll
        for (int q=0;q<2;q++){
            int j = j0 + tx + 16*q;
            float zi = acc[i][q][0] + zr[j];
            float zf = acc[i][q][1] + zr[256 + j];
            float zg = acc[i][q][2] + zr[512 + j];
            float zo = acc[i][q][3] + zr[768 + j];
            float ii = sigf(zi), ff = sigf(zf), gg = tanhf(zg), oo = sigf(zo);
            float c = ff * g_c[b*256 + j] + ii*gg;
            g_c[b*256 + j] = c;
            g_H[((t+1)*512 + b)*256 + j] = oo * tanhf(c);
        }
    }
}

// ---------------- all output projections + masked L1 loss in one GEMM ----------------
// M=65024 rows (r=t*512+b, uses g_H[t+1]), N=128, K=256; 64-row tiles stay within one t
__global__ __launch_bounds__(256) void k_loss(
    const float* __restrict__ values, const float* __restrict__ masks,
    const float* __restrict__ outW,   const float* __restrict__ outb)
{
    extern __shared__ float sm[];
    float* As = sm;              // [64][260]
    float* Bs = sm + 64*260;     // [128][260]
    const int r0 = blockIdx.x*64;
    const int t = r0 >> 9;
    const int tid = threadIdx.x;
#pragma unroll
    for (int q=0;q<16;q++){
        int i4 = tid + q*256;
        int row = i4 >> 6, c4 = i4 & 63;
        int r = r0 + row, b = r & 511;
        *(float4*)&As[row*260 + c4*4] = *(const float4*)&g_H[((t+1)*512 + b)*256 + c4*4];
    }
#pragma unroll
    for (int q=0;q<32;q++){
        int i4 = tid + q*256;
        int row = i4 >> 6, c4 = i4 & 63;
        *(float4*)&Bs[row*260 + c4*4] = *(const float4*)&outW[row*256 + c4*4];
    }
    __syncthreads();
    const int tx = tid & 15, ty = tid >> 4;
    float acc[4][8];
#pragma unroll
    for (int i=0;i<4;i++)
#pragma unroll
        for (int j=0;j<8;j++) acc[i][j]=0.f;
    for (int k0=0;k0<256;k0+=4){
        float4 a[4], w[8];
#pragma unroll
        for (int i=0;i<4;i++) a[i] = *(const float4*)&As[(ty+16*i)*260 + k0];
#pragma unroll
        for (int j=0;j<8;j++) w[j] = *(const float4*)&Bs[(tx+16*j)*260 + k0];
#pragma unroll
        for (int i=0;i<4;i++)
#pragma unroll
            for (int j=0;j<8;j++)
                acc[i][j] += a[i].x*w[j].x + a[i].y*w[j].y + a[i].z*w[j].z + a[i].w*w[j].w;
    }
    float local = 0.f;
#pragma unroll
    for (int i=0;i<4;i++){
        int r = r0 + ty + 16*i, b = r & 511;
#pragma unroll
        for (int j=0;j<8;j++){
            int f = tx + 16*j;
            float out = acc[i][j] + outb[f];
            int gi = (b*TT + (t+1))*FF + f;
            local += fabsf(values[gi] - out) * masks[gi];
        }
    }
    local *= g_invden[t];
    __syncthreads();               // done reading smem; reuse for reduction
    As[tid] = local;
    __syncthreads();
    for (int off = 128; off > 0; off >>= 1){
        if (tid < off) As[tid] += As[tid+off];
        __syncthreads();
    }
    if (tid == 0) atomicAdd(&g_loss, (double)As[0]);
}

// ---------------- gather outputs: [h_final | c_final | loss] ----------------
__global__ void k_final(float* __restrict__ out)
{
    int i = blockIdx.x*256 + threadIdx.x;
    if (i < BB*HH)            out[i] = g_H[NS*BB*HH + i];
    else if (i < 2*BB*HH)     out[i] = g_c[i - BB*HH];
    else if (i == 2*BB*HH)    out[i] = (float)g_loss;
}

// ---------------- launch ----------------
extern "C" void kernel_launch(void* const* d_in, const int* in_sizes, int n_in,
                              void* d_out, int out_size)
{
    const float* values = (const float*)d_in[0];
    const float* masks  = (const float*)d_in[1];
    const float* deltas = (const float*)d_in[2];
    const float* featW  = (const float*)d_in[3];
    const float* featb  = (const float*)d_in[4];
    const float* tempW  = (const float*)d_in[5];
    const float* tempb  = (const float*)d_in[6];
    const float* decayW = (const float*)d_in[7];
    const float* decayb = (const float*)d_in[8];
    const float* Wih    = (const float*)d_in[9];
    const float* Whh    = (const float*)d_in[10];
    const float* bih    = (const float*)d_in[11];
    const float* bhh    = (const float*)d_in[12];
    const float* outW   = (const float*)d_in[13];
    const float* outb   = (const float*)d_in[14];

    const int SM_VHAT  = 3*128*132*4;        // 202752
    const int SM_GAMMA = (128+64)*132*4;     // 101376
    const int SM_ZX    = 2*128*132*4;        // 135168
    const int SM_STEP  = (32+128)*260*4;     // 166400
    const int SM_LOSS  = (64+128)*260*4;     // 199680

    cudaFuncSetAttribute(k_vhat,  cudaFuncAttributeMaxDynamicSharedMemorySize, SM_VHAT);
    cudaFuncSetAttribute(k_gamma, cudaFuncAttributeMaxDynamicSharedMemorySize, SM_GAMMA);
    cudaFuncSetAttribute(k_zx,    cudaFuncAttributeMaxDynamicSharedMemorySize, SM_ZX);
    cudaFuncSetAttribute(k_step,  cudaFuncAttributeMaxDynamicSharedMemorySize, SM_STEP);
    cudaFuncSetAttribute(k_loss,  cudaFuncAttributeMaxDynamicSharedMemorySize, SM_LOSS);

    k_init<<<512, 256>>>();
    k_invden<<<NS, 256>>>(masks);
    k_vhat<<<BB, 256, SM_VHAT>>>(values, masks, featW, featb, tempW, tempb);
    k_gamma<<<dim3(BB*TT/128, HH/64), 256, SM_GAMMA>>>(deltas, decayW, decayb);
    k_zx<<<dim3(NS*BB/128, 4*HH/128), 256, SM_ZX>>>(masks, Wih, bih, bhh);
    for (int t = 0; t < NS; t++)
        k_step<<<dim3(16, 8), 128, SM_STEP>>>(Whh, t);
    k_loss<<<NS*BB/64, 256, SM_LOSS>>>(values, masks, outW, outb);
    k_final<<<(2*BB*HH + 1 + 255)/256, 256>>>((float*)d_out);
}

// round 11
// speedup vs baseline: 1.0007x; 1.0007x over previous
#include <cuda_runtime.h>
#include <math.h>

#define BB 512
#define TT 128
#define FF 128
#define HH 256
#define NS 127   // T-1 scan steps

// ---------------- scratch (static device memory; no allocations) ----------------
__device__ float g_vhat[BB*TT*FF];            // values_hat           [b][t][f]  (32MB)
__device__ float g_gamma[BB*TT*HH];           // gamma                [b][t][h]  (64MB)
__device__ float g_zx[NS*BB*4*HH];            // input-gate preact    [t][b][n]  (254MB)
__device__ float g_H[(NS+1)*BB*HH];           // h history, slot0=h0  [t][b][h]  (64MB)
__device__ float g_c[BB*HH];                  // cell state
__device__ float g_invden[NS];
__device__ double g_loss;

__device__ __forceinline__ float sigf(float x){ return 1.f/(1.f+expf(-x)); }

// ---------------- init: h0 = c0 = 0, loss = 0 ----------------
__global__ void k_init()
{
    int i = blockIdx.x*256 + threadIdx.x;
    if (i < BB*HH){ g_c[i] = 0.f; g_H[i] = 0.f; }
    if (i == 0) g_loss = 0.0;
}

// ---------------- per-step loss denominators: 1/(sum(masks[:,t+1])+1e-5) ----------------
__global__ void k_invden(const float* __restrict__ masks)
{
    int t = blockIdx.x;              // 0..126, uses masks at time t+1
    float s = 0.f;
    for (int i = threadIdx.x; i < BB*FF; i += 256){
        int b = i >> 7, f = i & 127;
        s += masks[(b*TT + (t+1))*FF + f];
    }
    __shared__ float red[256];
    red[threadIdx.x] = s; __syncthreads();
    for (int off = 128; off > 0; off >>= 1){
        if (threadIdx.x < off) red[threadIdx.x] += red[threadIdx.x+off];
        __syncthreads();
    }
    if (threadIdx.x == 0) g_invden[t] = 1.f/(red[0] + 1e-5f);
}

// ---------------- values_hat: feature + temporal regression fused ----------------
// one block per batch b; V, feat_W, temp_W all resident in smem (203KB)
__global__ __launch_bounds__(256) void k_vhat(
    const float* __restrict__ values, const float* __restrict__ masks,
    const float* __restrict__ featW,  const float* __restrict__ featb,
    const float* __restrict__ tempW,  const float* __restrict__ tempb)
{
    extern __shared__ float sm[];
    float* Vs = sm;                // [128][132]
    float* Wf = sm + 128*132;      // [128][132]
    float* Wt = sm + 2*128*132;    // [128][132]
    const int b = blockIdx.x, tid = threadIdx.x;
    const float4* v4 = (const float4*)(values + b*TT*FF);
    const float4* f4 = (const float4*)featW;
    const float4* t4 = (const float4*)tempW;
#pragma unroll
    for (int q = 0; q < 16; q++){
        int i4 = tid + q*256;
        int row = i4 >> 5, c4 = i4 & 31;
        *(float4*)&Vs[row*132 + c4*4] = v4[i4];
        *(float4*)&Wf[row*132 + c4*4] = f4[i4];
        *(float4*)&Wt[row*132 + c4*4] = t4[i4];
    }
    __syncthreads();
    const int tx = tid & 15, ty = tid >> 4;
    float acc[8][8];
#pragma unroll
    for (int i=0;i<8;i++)
#pragma unroll
        for (int j=0;j<8;j++) acc[i][j] = 0.f;

    // pass 1: acc[t][g] += V[t][k] * featW[g][k]
    for (int k0 = 0; k0 < 128; k0 += 4){
        float4 a[8], w[8];
#pragma unroll
        for (int i=0;i<8;i++) a[i] = *(const float4*)&Vs[(ty+16*i)*132 + k0];
#pragma unroll
        for (int j=0;j<8;j++) w[j] = *(const float4*)&Wf[(tx+16*j)*132 + k0];
#pragma unroll
        for (int i=0;i<8;i++)
#pragma unroll
            for (int j=0;j<8;j++)
                acc[i][j] += a[i].x*w[j].x + a[i].y*w[j].y + a[i].z*w[j].z + a[i].w*w[j].w;
    }
    // pass 2: acc[t][g] += tempW[t][s] * V[s][g]
    for (int k0 = 0; k0 < 128; k0 += 4){
        float4 a[8];
#pragma unroll
        for (int i=0;i<8;i++) a[i] = *(const float4*)&Wt[(ty+16*i)*132 + k0];
#pragma unroll
        for (int kk=0;kk<4;kk++){
            float vg[8];
#pragma unroll
            for (int j=0;j<8;j++) vg[j] = Vs[(k0+kk)*132 + tx + 16*j];
#pragma unroll
            for (int i=0;i<8;i++){
                float av = (kk==0)?a[i].x:(kk==1)?a[i].y:(kk==2)?a[i].z:a[i].w;
#pragma unroll
                for (int j=0;j<8;j++) acc[i][j] += av * vg[j];
            }
        }
    }
    const float* mrow = masks + b*TT*FF;
#pragma unroll
    for (int i=0;i<8;i++){
        int t = ty + 16*i;
        float tb  = tempb[t];
        float wtd = Wt[t*132 + t];
#pragma unroll
        for (int j=0;j<8;j++){
            int g = tx + 16*j;
            float v  = Vs[t*132 + g];
            float vh = acc[i][j] - v*(Wf[g*132 + g] + wtd) + featb[g] + tb;
            float m  = mrow[t*FF + g];
            g_vhat[(b*TT + t)*FF + g] = v*m + vh*(1.f - m);
        }
    }
}

// ---------------- gamma = exp(-|deltas @ decay_W^T + b|) ----------------
// tile: 128 rows x 64 h, K=128 resident
__global__ __launch_bounds__(256) void k_gamma(
    const float* __restrict__ deltas, const float* __restrict__ decayW,
    const float* __restrict__ decayb)
{
    extern __shared__ float sm[];
    float* As = sm;               // [128][132]
    float* Bs = sm + 128*132;     // [64][132]
    const int r0 = blockIdx.x*128, h0 = blockIdx.y*64, tid = threadIdx.x;
    const float4* a4 = (const float4*)(deltas + r0*FF);
#pragma unroll
    for (int q=0;q<16;q++){
        int i4 = tid + q*256;
        int row = i4 >> 5, c4 = i4 & 31;
        *(float4*)&As[row*132 + c4*4] = a4[i4];
    }
    const float4* b4 = (const float4*)(decayW + h0*FF);
#pragma unroll
    for (int q=0;q<8;q++){
        int i4 = tid + q*256;
        int row = i4 >> 5, c4 = i4 & 31;
        *(float4*)&Bs[row*132 + c4*4] = b4[i4];
    }
    __syncthreads();
    const int tx = tid & 15, ty = tid >> 4;
    float acc[8][4];
#pragma unroll
    for (int i=0;i<8;i++)
#pragma unroll
        for (int q=0;q<4;q++) acc[i][q]=0.f;
    for (int k0=0;k0<128;k0+=4){
        float4 a[8], w[4];
#pragma unroll
        for (int i=0;i<8;i++) a[i] = *(const float4*)&As[(ty+16*i)*132 + k0];
#pragma unroll
        for (int q=0;q<4;q++) w[q] = *(const float4*)&Bs[(tx+16*q)*132 + k0];
#pragma unroll
        for (int i=0;i<8;i++)
#pragma unroll
            for (int q=0;q<4;q++)
                acc[i][q] += a[i].x*w[q].x + a[i].y*w[q].y + a[i].z*w[q].z + a[i].w*w[q].w;
    }
#pragma unroll
    for (int i=0;i<8;i++){
        int r = r0 + ty + 16*i;
#pragma unroll
        for (int q=0;q<4;q++){
            int h = h0 + tx + 16*q;
            g_gamma[r*HH + h] = expf(-fabsf(acc[i][q] + decayb[h]));
        }
    }
}

// ---------------- zx = [values_hat, masks] @ W_ih^T + b_ih + b_hh (all steps at once) ----------------
// M=65024 (r=t*512+b), N=1024, K=256 (2 chunks of 128)
__global__ __launch_bounds__(256) void k_zx(
    const float* __restrict__ masks, const float* __restrict__ Wih,
    const float* __restrict__ bih,   const float* __restrict__ bhh)
{
    extern __shared__ float sm[];
    float* As = sm;               // [128][132]
    float* Bs = sm + 128*132;     // [128][132]
    const int r0 = blockIdx.x*128, n0 = blockIdx.y*128, tid = threadIdx.x;
    const int tx = tid & 15, ty = tid >> 4;
    float acc[8][8];
#pragma unroll
    for (int i=0;i<8;i++)
#pragma unroll
        for (int j=0;j<8;j++) acc[i][j]=0.f;

    for (int kc = 0; kc < 2; kc++){
#pragma unroll
        for (int q=0;q<16;q++){
            int i4 = tid + q*256;
            int row = i4 >> 5, c4 = i4 & 31;
            int r = r0 + row;
            int t = r >> 9, b = r & 511;
            const float* src = (kc==0) ? g_vhat : masks;
            *(float4*)&As[row*132 + c4*4] = *(const float4*)&src[(b*TT + t)*FF + c4*4];
            *(float4*)&Bs[row*132 + c4*4] = *(const float4*)&Wih[(n0+row)*256 + kc*128 + c4*4];
        }
        __syncthreads();
        for (int k0=0;k0<128;k0+=4){
            float4 a[8], w[8];
#pragma unroll
            for (int i=0;i<8;i++) a[i] = *(const float4*)&As[(ty+16*i)*132 + k0];
#pragma unroll
            for (int j=0;j<8;j++) w[j] = *(const float4*)&Bs[(tx+16*j)*132 + k0];
#pragma unroll
            for (int i=0;i<8;i++)
#pragma unroll
                for (int j=0;j<8;j++)
                    acc[i][j] += a[i].x*w[j].x + a[i].y*w[j].y + a[i].z*w[j].z + a[i].w*w[j].w;
        }
        __syncthreads();
    }
#pragma unroll
    for (int i=0;i<8;i++){
        int r = r0 + ty + 16*i;
#pragma unroll
        for (int j=0;j<8;j++){
            int n = n0 + tx + 16*j;
            g_zx[r*1024 + n] = acc[i][j] + bih[n] + bhh[n];
        }
    }
}

// ---------------- one LSTM scan step: h' , c' from h*gamma, zx[t], W_hh ----------------
// grid (16,8): b-tile 32, j-tile 32 (x4 gates). 128 threads, 166KB smem.
__global__ __launch_bounds__(128) void k_step(const float* __restrict__ Whh, int t)
{
    extern __shared__ float sm[];
    float* hs = sm;              // [32][260]  decayed h
    float* ws = sm + 32*260;     // [128][260] 4 gates x 32 j rows of W_hh
    const int b0 = blockIdx.x*32, j0 = blockIdx.y*32, tid = threadIdx.x;
#pragma unroll
    for (int q=0;q<16;q++){
        int i4 = tid + q*128;
        int row = i4 >> 6, c4 = i4 & 63;
        int b = b0 + row;
        float4 hv = *(const float4*)&g_H[(t*512 + b)*256 + c4*4];
        float4 gv = *(const float4*)&g_gamma[(b*TT + t)*HH + c4*4];
        float4 o; o.x=hv.x*gv.x; o.y=hv.y*gv.y; o.z=hv.z*gv.z; o.w=hv.w*gv.w;
        *(float4*)&hs[row*260 + c4*4] = o;
    }
#pragma unroll
    for (int q=0;q<64;q++){
        int i4 = tid + q*128;
        int row = i4 >> 6, c4 = i4 & 63;
        int gate = row >> 5, jj = row & 31;
        *(float4*)&ws[row*260 + c4*4] = *(const float4*)&Whh[(gate*256 + j0 + jj)*256 + c4*4];
    }
    __syncthreads();
    const int tx = tid & 15, ty = tid >> 4;   // ty 0..7
    float acc[4][2][4];
#pragma unroll
    for (int i=0;i<4;i++)
#pragma unroll
        for (int q=0;q<2;q++)
#pragma unroll
            for (int g=0;g<4;g++) acc[i][q][g]=0.f;

    for (int k0=0;k0<256;k0+=4){
        float4 a[4];
#pragma unroll
        for (int i=0;i<4;i++) a[i] = *(const float4*)&hs[(ty*4+i)*260 + k0];
#pragma unroll
        for (int q=0;q<2;q++)
#pragma unroll
            for (int g=0;g<4;g++){
                float4 w = *(const float4*)&ws[(g*32 + tx + 16*q)*260 + k0];
#pragma unroll
                for (int i=0;i<4;i++)
                    acc[i][q][g] += a[i].x*w.x + a[i].y*w.y + a[i].z*w.z + a[i].w*w.w;
            }
    }
#pragma unroll
    for (int i=0;i<4;i++){
        int b = b0 + ty*4 + i;
        const float* zr = g_zx + (t*512 + b)*1024;
#pragma unroll
        for (int q=0;q<2;q++){
            int j = j0 + tx + 16*q;
            float zi = acc[i][q][0] + zr[j];
            float zf = acc[i][q][1] + zr[256 + j];
            float zg = acc[i][q][2] + zr[512 + j];
            float zo = acc[i][q][3] + zr[768 + j];
            float ii = sigf(zi), ff = sigf(zf), gg = tanhf(zg), oo = sigf(zo);
            float c = ff * g_c[b*256 + j] + ii*gg;
            g_c[b*256 + j] = c;
            g_H[((t+1)*512 + b)*256 + j] = oo * tanhf(c);
        }
    }
}

// ---------------- all output projections + masked L1 loss in one GEMM ----------------
// M=65024 rows (r=t*512+b, uses g_H[t+1]), N=128, K=256; 64-row tiles stay within one t
__global__ __launch_bounds__(256) void k_loss(
    const float* __restrict__ values, const float* __restrict__ masks,
    const float* __restrict__ outW,   const float* __restrict__ outb)
{
    extern __shared__ float sm[];
    float* As = sm;              // [64][260]
    float* Bs = sm + 64*260;     // [128][260]
    const int r0 = blockIdx.x*64;
    const int t = r0 >> 9;
    const int tid = threadIdx.x;
#pragma unroll
    for (int q=0;q<16;q++){
        int i4 = tid + q*256;
        int row = i4 >> 6, c4 = i4 & 63;
        int r = r0 + row, b = r & 511;
        *(float4*)&As[row*260 + c4*4] = *(const float4*)&g_H[((t+1)*512 + b)*256 + c4*4];
    }
#pragma unroll
    for (int q=0;q<32;q++){
        int i4 = tid + q*256;
        int row = i4 >> 6, c4 = i4 & 63;
        *(float4*)&Bs[row*260 + c4*4] = *(const float4*)&outW[row*256 + c4*4];
    }
    __syncthreads();
    const int tx = tid & 15, ty = tid >> 4;
    float acc[4][8];
#pragma unroll
    for (int i=0;i<4;i++)
#pragma unroll
        for (int j=0;j<8;j++) acc[i][j]=0.f;
    for (int k0=0;k0<256;k0+=4){
        float4 a[4], w[8];
#pragma unroll
        for (int i=0;i<4;i++) a[i] = *(const float4*)&As[(ty+16*i)*260 + k0];
#pragma unroll
        for (int j=0;j<8;j++) w[j] = *(const float4*)&Bs[(tx+16*j)*260 + k0];
#pragma unroll
        for (int i=0;i<4;i++)
#pragma unroll
            for (int j=0;j<8;j++)
                acc[i][j] += a[i].x*w[j].x + a[i].y*w[j].y + a[i].z*w[j].z + a[i].w*w[j].w;
    }
    float local = 0.f;
#pragma unroll
    for (int i=0;i<4;i++){
        int r = r0 + ty + 16*i, b = r & 511;
#pragma unroll
        for (int j=0;j<8;j++){
            int f = tx + 16*j;
            float out = acc[i][j] + outb[f];
            int gi = (b*TT + (t+1))*FF + f;
            local += fabsf(values[gi] - out) * masks[gi];
        }
    }
    local *= g_invden[t];
    __syncthreads();               // done reading smem; reuse for reduction
    As[tid] = local;
    __syncthreads();
    for (int off = 128; off > 0; off >>= 1){
        if (tid < off) As[tid] += As[tid+off];
        __syncthreads();
    }
    if (tid == 0) atomicAdd(&g_loss, (double)As[0]);
}

// ---------------- gather outputs: [h_final | c_final | loss] ----------------
__global__ void k_final(float* __restrict__ out)
{
    int i = blockIdx.x*256 + threadIdx.x;
    if (i < BB*HH)            out[i] = g_H[NS*BB*HH + i];
    else if (i < 2*BB*HH)     out[i] = g_c[i - BB*HH];
    else if (i == 2*BB*HH)    out[i] = (float)g_loss;
}

// ---------------- launch ----------------
extern "C" void kernel_launch(void* const* d_in, const int* in_sizes, int n_in,
                              void* d_out, int out_size)
{
    const float* values = (const float*)d_in[0];
    const float* masks  = (const float*)d_in[1];
    const float* deltas = (const float*)d_in[2];
    const float* featW  = (const float*)d_in[3];
    const float* featb  = (const float*)d_in[4];
    const float* tempW  = (const float*)d_in[5];
    const float* tempb  = (const float*)d_in[6];
    const float* decayW = (const float*)d_in[7];
    const float* decayb = (const float*)d_in[8];
    const float* Wih    = (const float*)d_in[9];
    const float* Whh    = (const float*)d_in[10];
    const float* bih    = (const float*)d_in[11];
    const float* bhh    = (const float*)d_in[12];
    const float* outW   = (const float*)d_in[13];
    const float* outb   = (const float*)d_in[14];

    const int SM_VHAT  = 3*128*132*4;        // 202752
    const int SM_GAMMA = (128+64)*132*4;     // 101376
    const int SM_ZX    = 2*128*132*4;        // 135168
    const int SM_STEP  = (32+128)*260*4;     // 166400
    const int SM_LOSS  = (64+128)*260*4;     // 199680

    cudaFuncSetAttribute(k_vhat,  cudaFuncAttributeMaxDynamicSharedMemorySize, SM_VHAT);
    cudaFuncSetAttribute(k_gamma, cudaFuncAttributeMaxDynamicSharedMemorySize, SM_GAMMA);
    cudaFuncSetAttribute(k_zx,    cudaFuncAttributeMaxDynamicSharedMemorySize, SM_ZX);
    cudaFuncSetAttribute(k_step,  cudaFuncAttributeMaxDynamicSharedMemorySize, SM_STEP);
    cudaFuncSetAttribute(k_loss,  cudaFuncAttributeMaxDynamicSharedMemorySize, SM_LOSS);

    k_init<<<512, 256>>>();
    k_invden<<<NS, 256>>>(masks);
    k_vhat<<<BB, 256, SM_VHAT>>>(values, masks, featW, featb, tempW, tempb);
    k_gamma<<<dim3(BB*TT/128, HH/64), 256, SM_GAMMA>>>(deltas, decayW, decayb);
    k_zx<<<dim3(NS*BB/128, 4*HH/128), 256, SM_ZX>>>(masks, Wih, bih, bhh);
    for (int t = 0; t < NS; t++)
        k_step<<<dim3(16, 8), 128, SM_STEP>>>(Whh, t);
    k_loss<<<NS*BB/64, 256, SM_LOSS>>>(values, masks, outW, outb);
    k_final<<<(2*BB*HH + 1 + 255)/256, 256>>>((float*)d_out);
}

// round 12
// speedup vs baseline: 1.0022x; 1.0015x over previous
#include <cuda_runtime.h>
#include <math.h>

#define BB 512
#define TT 128
#define FF 128
#define HH 256
#define NS 127   // T-1 scan steps

// ---------------- scratch (static device memory; no allocations) ----------------
__device__ float g_vhat[BB*TT*FF];            // values_hat           [b][t][f]  (32MB)
__device__ float g_gamma[BB*TT*HH];           // gamma                [b][t][h]  (64MB)
__device__ float g_zx[NS*BB*4*HH];            // input-gate preact    [t][b][n]  (254MB)
__device__ float g_H[(NS+1)*BB*HH];           // h history, slot0=h0  [t][b][h]  (64MB)
__device__ float g_c[BB*HH];                  // cell state
__device__ float g_invden[NS];
__device__ double g_loss;

__device__ __forceinline__ float sigf(float x){ return 1.f/(1.f+expf(-x)); }

// ---------------- init: h0 = c0 = 0, loss = 0 ----------------
__global__ void k_init()
{
    int i = blockIdx.x*256 + threadIdx.x;
    if (i < BB*HH){ g_c[i] = 0.f; g_H[i] = 0.f; }
    if (i == 0) g_loss = 0.0;
}

// ---------------- per-step loss denominators: 1/(sum(masks[:,t+1])+1e-5) ----------------
__global__ void k_invden(const float* __restrict__ masks)
{
    int t = blockIdx.x;              // 0..126, uses masks at time t+1
    float s = 0.f;
    for (int i = threadIdx.x; i < BB*FF; i += 256){
        int b = i >> 7, f = i & 127;
        s += masks[(b*TT + (t+1))*FF + f];
    }
    __shared__ float red[256];
    red[threadIdx.x] = s; __syncthreads();
    for (int off = 128; off > 0; off >>= 1){
        if (threadIdx.x < off) red[threadIdx.x] += red[threadIdx.x+off];
        __syncthreads();
    }
    if (threadIdx.x == 0) g_invden[t] = 1.f/(red[0] + 1e-5f);
}

// ---------------- values_hat: feature + temporal regression fused ----------------
// one block per batch b; V, feat_W, temp_W all resident in smem (203KB)
__global__ __launch_bounds__(256) void k_vhat(
    const float* __restrict__ values, const float* __restrict__ masks,
    const float* __restrict__ featW,  const float* __restrict__ featb,
    const float* __restrict__ tempW,  const float* __restrict__ tempb)
{
    extern __shared__ float sm[];
    float* Vs = sm;                // [128][132]
    float* Wf = sm + 128*132;      // [128][132]
    float* Wt = sm + 2*128*132;    // [128][132]
    const int b = blockIdx.x, tid = threadIdx.x;
    const float4* v4 = (const float4*)(values + b*TT*FF);
    const float4* f4 = (const float4*)featW;
    const float4* t4 = (const float4*)tempW;
#pragma unroll
    for (int q = 0; q < 16; q++){
        int i4 = tid + q*256;
        int row = i4 >> 5, c4 = i4 & 31;
        *(float4*)&Vs[row*132 + c4*4] = v4[i4];
        *(float4*)&Wf[row*132 + c4*4] = f4[i4];
        *(float4*)&Wt[row*132 + c4*4] = t4[i4];
    }
    __syncthreads();
    const int tx = tid & 15, ty = tid >> 4;
    float acc[8][8];
#pragma unroll
    for (int i=0;i<8;i++)
#pragma unroll
        for (int j=0;j<8;j++) acc[i][j] = 0.f;

    // pass 1: acc[t][g] += V[t][k] * featW[g][k]
    for (int k0 = 0; k0 < 128; k0 += 4){
        float4 a[8], w[8];
#pragma unroll
        for (int i=0;i<8;i++) a[i] = *(const float4*)&Vs[(ty+16*i)*132 + k0];
#pragma unroll
        for (int j=0;j<8;j++) w[j] = *(const float4*)&Wf[(tx+16*j)*132 + k0];
#pragma unroll
        for (int i=0;i<8;i++)
#pragma unroll
            for (int j=0;j<8;j++)
                acc[i][j] += a[i].x*w[j].x + a[i].y*w[j].y + a[i].z*w[j].z + a[i].w*w[j].w;
    }
    // pass 2: acc[t][g] += tempW[t][s] * V[s][g]
    for (int k0 = 0; k0 < 128; k0 += 4){
        float4 a[8];
#pragma unroll
        for (int i=0;i<8;i++) a[i] = *(const float4*)&Wt[(ty+16*i)*132 + k0];
#pragma unroll
        for (int kk=0;kk<4;kk++){
            float vg[8];
#pragma unroll
            for (int j=0;j<8;j++) vg[j] = Vs[(k0+kk)*132 + tx + 16*j];
#pragma unroll
            for (int i=0;i<8;i++){
                float av = (kk==0)?a[i].x:(kk==1)?a[i].y:(kk==2)?a[i].z:a[i].w;
#pragma unroll
                for (int j=0;j<8;j++) acc[i][j] += av * vg[j];
            }
        }
    }
    const float* mrow = masks + b*TT*FF;
#pragma unroll
    for (int i=0;i<8;i++){
        int t = ty + 16*i;
        float tb  = tempb[t];
        float wtd = Wt[t*132 + t];
#pragma unroll
        for (int j=0;j<8;j++){
            int g = tx + 16*j;
            float v  = Vs[t*132 + g];
            float vh = acc[i][j] - v*(Wf[g*132 + g] + wtd) + featb[g] + tb;
            float m  = mrow[t*FF + g];
            g_vhat[(b*TT + t)*FF + g] = v*m + vh*(1.f - m);
        }
    }
}

// ---------------- gamma = exp(-|deltas @ decay_W^T + b|) ----------------
// tile: 128 rows x 64 h, K=128 resident
__global__ __launch_bounds__(256) void k_gamma(
    const float* __restrict__ deltas, const float* __restrict__ decayW,
    const float* __restrict__ decayb)
{
    extern __shared__ float sm[];
    float* As = sm;               // [128][132]
    float* Bs = sm + 128*132;     // [64][132]
    const int r0 = blockIdx.x*128, h0 = blockIdx.y*64, tid = threadIdx.x;
    const float4* a4 = (const float4*)(deltas + r0*FF);
#pragma unroll
    for (int q=0;q<16;q++){
        int i4 = tid + q*256;
        int row = i4 >> 5, c4 = i4 & 31;
        *(float4*)&As[row*132 + c4*4] = a4[i4];
    }
    const float4* b4 = (const float4*)(decayW + h0*FF);
#pragma unroll
    for (int q=0;q<8;q++){
        int i4 = tid + q*256;
        int row = i4 >> 5, c4 = i4 & 31;
        *(float4*)&Bs[row*132 + c4*4] = b4[i4];
    }
    __syncthreads();
    const int tx = tid & 15, ty = tid >> 4;
    float acc[8][4];
#pragma unroll
    for (int i=0;i<8;i++)
#pragma unroll
        for (int q=0;q<4;q++) acc[i][q]=0.f;
    for (int k0=0;k0<128;k0+=4){
        float4 a[8], w[4];
#pragma unroll
        for (int i=0;i<8;i++) a[i] = *(const float4*)&As[(ty+16*i)*132 + k0];
#pragma unroll
        for (int q=0;q<4;q++) w[q] = *(const float4*)&Bs[(tx+16*q)*132 + k0];
#pragma unroll
        for (int i=0;i<8;i++)
#pragma unroll
            for (int q=0;q<4;q++)
                acc[i][q] += a[i].x*w[q].x + a[i].y*w[q].y + a[i].z*w[q].z + a[i].w*w[q].w;
    }
#pragma unroll
    for (int i=0;i<8;i++){
        int r = r0 + ty + 16*i;
#pragma unroll
        for (int q=0;q<4;q++){
            int h = h0 + tx + 16*q;
            g_gamma[r*HH + h] = expf(-fabsf(acc[i][q] + decayb[h]));
        }
    }
}

// ---------------- zx = [values_hat, masks] @ W_ih^T + b_ih + b_hh (all steps at once) ----------------
// M=65024 (r=t*512+b), N=1024, K=256 (2 chunks of 128)
__global__ __launch_bounds__(256) void k_zx(
    const float* __restrict__ masks, const float* __restrict__ Wih,
    const float* __restrict__ bih,   const float* __restrict__ bhh)
{
    extern __shared__ float sm[];
    float* As = sm;               // [128][132]
    float* Bs = sm + 128*132;     // [128][132]
    const int r0 = blockIdx.x*128, n0 = blockIdx.y*128, tid = threadIdx.x;
    const int tx = tid & 15, ty = tid >> 4;
    float acc[8][8];
#pragma unroll
    for (int i=0;i<8;i++)
#pragma unroll
        for (int j=0;j<8;j++) acc[i][j]=0.f;

    for (int kc = 0; kc < 2; kc++){
#pragma unroll
        for (int q=0;q<16;q++){
            int i4 = tid + q*256;
            int row = i4 >> 5, c4 = i4 & 31;
            int r = r0 + row;
            int t = r >> 9, b = r & 511;
            const float* src = (kc==0) ? g_vhat : masks;
            *(float4*)&As[row*132 + c4*4] = *(const float4*)&src[(b*TT + t)*FF + c4*4];
            *(float4*)&Bs[row*132 + c4*4] = *(const float4*)&Wih[(n0+row)*256 + kc*128 + c4*4];
        }
        __syncthreads();
        for (int k0=0;k0<128;k0+=4){
            float4 a[8], w[8];
#pragma unroll
            for (int i=0;i<8;i++) a[i] = *(const float4*)&As[(ty+16*i)*132 + k0];
#pragma unroll
            for (int j=0;j<8;j++) w[j] = *(const float4*)&Bs[(tx+16*j)*132 + k0];
#pragma unroll
            for (int i=0;i<8;i++)
#pragma unroll
                for (int j=0;j<8;j++)
                    acc[i][j] += a[i].x*w[j].x + a[i].y*w[j].y + a[i].z*w[j].z + a[i].w*w[j].w;
        }
        __syncthreads();
    }
#pragma unroll
    for (int i=0;i<8;i++){
        int r = r0 + ty + 16*i;
#pragma unroll
        for (int j=0;j<8;j++){
            int n = n0 + tx + 16*j;
            g_zx[r*1024 + n] = acc[i][j] + bih[n] + bhh[n];
        }
    }
}

// ---------------- one LSTM scan step: h' , c' from h*gamma, zx[t], W_hh ----------------
// grid (16,8): b-tile 32, j-tile 32 (x4 gates). 128 threads, 166KB smem.
__global__ __launch_bounds__(128) void k_step(const float* __restrict__ Whh, int t)
{
    extern __shared__ float sm[];
    float* hs = sm;              // [32][260]  decayed h
    float* ws = sm + 32*260;     // [128][260] 4 gates x 32 j rows of W_hh
    const int b0 = blockIdx.x*32, j0 = blockIdx.y*32, tid = threadIdx.x;
#pragma unroll
    for (int q=0;q<16;q++){
        int i4 = tid + q*128;
        int row = i4 >> 6, c4 = i4 & 63;
        int b = b0 + row;
        float4 hv = *(const float4*)&g_H[(t*512 + b)*256 + c4*4];
        float4 gv = *(const float4*)&g_gamma[(b*TT + t)*HH + c4*4];
        float4 o; o.x=hv.x*gv.x; o.y=hv.y*gv.y; o.z=hv.z*gv.z; o.w=hv.w*gv.w;
        *(float4*)&hs[row*260 + c4*4] = o;
    }
#pragma unroll
    for (int q=0;q<64;q++){
        int i4 = tid + q*128;
        int row = i4 >> 6, c4 = i4 & 63;
        int gate = row >> 5, jj = row & 31;
        *(float4*)&ws[row*260 + c4*4] = *(const float4*)&Whh[(gate*256 + j0 + jj)*256 + c4*4];
    }
    __syncthreads();
    const int tx = tid & 15, ty = tid >> 4;   // ty 0..7
    float acc[4][2][4];
#pragma unroll
    for (int i=0;i<4;i++)
#pragma unroll
        for (int q=0;q<2;q++)
#pragma unroll
            for (int g=0;g<4;g++) acc[i][q][g]=0.f;

    for (int k0=0;k0<256;k0+=4){
        float4 a[4];
#pragma unroll
        for (int i=0;i<4;i++) a[i] = *(const float4*)&hs[(ty*4+i)*260 + k0];
#pragma unroll
        for (int q=0;q<2;q++)
#pragma unroll
            for (int g=0;g<4;g++){
                float4 w = *(const float4*)&ws[(g*32 + tx + 16*q)*260 + k0];
#pragma unroll
                for (int i=0;i<4;i++)
                    acc[i][q][g] += a[i].x*w.x + a[i].y*w.y + a[i].z*w.z + a[i].w*w.w;
            }
    }
#pragma unroll
    for (int i=0;i<4;i++){
        int b = b0 + ty*4 + i;
        const float* zr = g_zx + (t*512 + b)*1024;
#pragma unroll
        for (int q=0;q<2;q++){
            int j = j0 + tx + 16*q;
            float zi = acc[i][q][0] + zr[j];
            float zf = acc[i][q][1] + zr[256 + j];
            float zg = acc[i][q][2] + zr[512 + j];
            float zo = acc[i][q][3] + zr[768 + j];
            float ii = sigf(zi), ff = sigf(zf), gg = tanhf(zg), oo = sigf(zo);
            float c = ff * g_c[b*256 + j] + ii*gg;
            g_c[b*256 + j] = c;
            g_H[((t+1)*512 + b)*256 + j] = oo * tanhf(c);
        }
    }
}

// ---------------- all output projections + masked L1 loss in one GEMM ----------------
// M=65024 rows (r=t*512+b, uses g_H[t+1]), N=128, K=256; 64-row tiles stay within one t
__global__ __launch_bounds__(256) void k_loss(
    const float* __restrict__ values, const float* __restrict__ masks,
    const float* __restrict__ outW,   const float* __restrict__ outb)
{
    extern __shared__ float sm[];
    float* As = sm;              // [64][260]
    float* Bs = sm + 64*260;     // [128][260]
    const int r0 = blockIdx.x*64;
    const int t = r0 >> 9;
    const int tid = threadIdx.x;
#pragma unroll
    for (int q=0;q<16;q++){
        int i4 = tid + q*256;
        int row = i4 >> 6, c4 = i4 & 63;
        int r = r0 + row, b = r & 511;
        *(float4*)&As[row*260 + c4*4] = *(const float4*)&g_H[((t+1)*512 + b)*256 + c4*4];
    }
#pragma unroll
    for (int q=0;q<32;q++){
        int i4 = tid + q*256;
        int row = i4 >> 6, c4 = i4 & 63;
        *(float4*)&Bs[row*260 + c4*4] = *(const float4*)&outW[row*256 + c4*4];
    }
    __syncthreads();
    const int tx = tid & 15, ty = tid >> 4;
    float acc[4][8];
#pragma unroll
    for (int i=0;i<4;i++)
#pragma unroll
        for (int j=0;j<8;j++) acc[i][j]=0.f;
    for (int k0=0;k0<256;k0+=4){
        float4 a[4], w[8];
#pragma unroll
        for (int i=0;i<4;i++) a[i] = *(const float4*)&As[(ty+16*i)*260 + k0];
#pragma unroll
        for (int j=0;j<8;j++) w[j] = *(const float4*)&Bs[(tx+16*j)*260 + k0];
#pragma unroll
        for (int i=0;i<4;i++)
#pragma unroll
            for (int j=0;j<8;j++)
                acc[i][j] += a[i].x*w[j].x + a[i].y*w[j].y + a[i].z*w[j].z + a[i].w*w[j].w;
    }
    float local = 0.f;
#pragma unroll
    for (int i=0;i<4;i++){
        int r = r0 + ty + 16*i, b = r & 511;
#pragma unroll
        for (int j=0;j<8;j++){
            int f = tx + 16*j;
            float out = acc[i][j] + outb[f];
            int gi = (b*TT + (t+1))*FF + f;
            local += fabsf(values[gi] - out) * masks[gi];
        }
    }
    local *= g_invden[t];
    __syncthreads();               // done reading smem; reuse for reduction
    As[tid] = local;
    __syncthreads();
    for (int off = 128; off > 0; off >>= 1){
        if (tid < off) As[tid] += As[tid+off];
        __syncthreads();
    }
    if (tid == 0) atomicAdd(&g_loss, (double)As[0]);
}

// ---------------- gather outputs: [h_final | c_final | loss] ----------------
__global__ void k_final(float* __restrict__ out)
{
    int i = blockIdx.x*256 + threadIdx.x;
    if (i < BB*HH)            out[i] = g_H[NS*BB*HH + i];
    else if (i < 2*BB*HH)     out[i] = g_c[i - BB*HH];
    else if (i == 2*BB*HH)    out[i] = (float)g_loss;
}

// ---------------- launch ----------------
extern "C" void kernel_launch(void* const* d_in, const int* in_sizes, int n_in,
                              void* d_out, int out_size)
{
    const float* values = (const float*)d_in[0];
    const float* masks  = (const float*)d_in[1];
    const float* deltas = (const float*)d_in[2];
    const float* featW  = (const float*)d_in[3];
    const float* featb  = (const float*)d_in[4];
    const float* tempW  = (const float*)d_in[5];
    const float* tempb  = (const float*)d_in[6];
    const float* decayW = (const float*)d_in[7];
    const float* decayb = (const float*)d_in[8];
    const float* Wih    = (const float*)d_in[9];
    const float* Whh    = (const float*)d_in[10];
    const float* bih    = (const float*)d_in[11];
    const float* bhh    = (const float*)d_in[12];
    const float* outW   = (const float*)d_in[13];
    const float* outb   = (const float*)d_in[14];

    const int SM_VHAT  = 3*128*132*4;        // 202752
    const int SM_GAMMA = (128+64)*132*4;     // 101376
    const int SM_ZX    = 2*128*132*4;        // 135168
    const int SM_STEP  = (32+128)*260*4;     // 166400
    const int SM_LOSS  = (64+128)*260*4;     // 199680

    cudaFuncSetAttribute(k_vhat,  cudaFuncAttributeMaxDynamicSharedMemorySize, SM_VHAT);
    cudaFuncSetAttribute(k_gamma, cudaFuncAttributeMaxDynamicSharedMemorySize, SM_GAMMA);
    cudaFuncSetAttribute(k_zx,    cudaFuncAttributeMaxDynamicSharedMemorySize, SM_ZX);
    cudaFuncSetAttribute(k_step,  cudaFuncAttributeMaxDynamicSharedMemorySize, SM_STEP);
    cudaFuncSetAttribute(k_loss,  cudaFuncAttributeMaxDynamicSharedMemorySize, SM_LOSS);

    k_init<<<512, 256>>>();
    k_invden<<<NS, 256>>>(masks);
    k_vhat<<<BB, 256, SM_VHAT>>>(values, masks, featW, featb, tempW, tempb);
    k_gamma<<<dim3(BB*TT/128, HH/64), 256, SM_GAMMA>>>(deltas, decayW, decayb);
    k_zx<<<dim3(NS*BB/128, 4*HH/128), 256, SM_ZX>>>(masks, Wih, bih, bhh);
    for (int t = 0; t < NS; t++)
        k_step<<<dim3(16, 8), 128, SM_STEP>>>(Whh, t);
    k_loss<<<NS*BB/64, 256, SM_LOSS>>>(values, masks, outW, outb);
    k_final<<<(2*BB*HH + 1 + 255)/256, 256>>>((float*)d_out);
}